// round 16
// baseline (speedup 1.0000x reference)
#include <cuda_runtime.h>
#include <math.h>
#include <stdint.h>

typedef unsigned long long u64;

#define BB 32
#define TT 256
#define DD 512
#define VV 32000
#define MR (BB*TT)        // 8192 token rows
#define NSTEP (TT-3)      // 253 scan steps

// ======================= device scratch (fragment-ordered operands) =======================
__device__ __align__(256) float gAhi[MR * DD];
__device__ __align__(256) float gAlo[MR * DD];
__device__ __align__(256) float gYhi[MR * 1024];
__device__ __align__(256) float gYlo[MR * 1024];
__device__ __align__(256) float gW1[1024 * 512];
__device__ __align__(256) float gW2[512 * 1024];
__device__ float g_X[MR * DD];        // pre-LN residual (fp32)
__device__ float g_mu[MR];            // LN mean per row
__device__ float g_rs[MR];            // LN rstd per row
__device__ float g_ws[MR];
__device__ float g_dm[MR];
__device__ float g_q[BB * DD];
__device__ float g_ctxT[DD * BB];

// ======================= helpers =======================
__device__ __forceinline__ float to_tf32(float x) {
    float r; asm("cvt.rna.tf32.f32 %0, %1;" : "=f"(r) : "f"(x)); return r;
}
__device__ __forceinline__ void split2(float v, float& hi, float& lo) {
    hi = to_tf32(v);
    lo = v - hi;
}
__device__ __forceinline__ float trunc_lo(float v) {
    uint32_t m = __float_as_uint(v) & 0xFFFFE000u;
    return v - __uint_as_float(m);
}
__device__ __forceinline__ uint32_t smem_u32(const void* p) {
    uint32_t a;
    asm("{ .reg .u64 t; cvta.to.shared.u64 t, %1; cvt.u32.u64 %0, t; }" : "=r"(a) : "l"(p));
    return a;
}
__device__ __forceinline__ void cp16(uint32_t dst, const void* src) {
    asm volatile("cp.async.cg.shared.global [%0], [%1], 16;" :: "r"(dst), "l"(src));
}
#define CP_COMMIT() asm volatile("cp.async.commit_group;" ::: "memory")
#define CP_WAIT(n)  asm volatile("cp.async.wait_group %0;" :: "n"(n) : "memory")

__device__ __forceinline__ void mma8(float* c, uint4 a, uint2 b) {
    asm volatile(
        "mma.sync.aligned.m16n8k8.row.col.f32.tf32.tf32.f32 "
        "{%0,%1,%2,%3}, {%4,%5,%6,%7}, {%8,%9}, {%0,%1,%2,%3};"
        : "+f"(c[0]), "+f"(c[1]), "+f"(c[2]), "+f"(c[3])
        : "r"(a.x), "r"(a.y), "r"(a.z), "r"(a.w), "r"(b.x), "r"(b.y));
}

__device__ __forceinline__ u64 pack_dup(float x) {
    u64 r; asm("mov.b64 %0, {%1, %1};" : "=l"(r) : "f"(x)); return r;
}
__device__ __forceinline__ u64 ffma2(u64 a, u64 b, u64 c) {
    u64 d; asm("fma.rn.f32x2 %0, %1, %2, %3;" : "=l"(d) : "l"(a), "l"(b), "l"(c)); return d;
}
__device__ __forceinline__ void unpack2(u64 v, float& lo, float& hi) {
    asm("mov.b64 {%0, %1}, %2;" : "=f"(lo), "=f"(hi) : "l"(v));
}

// ======================= prep: tokens -> split A fragments (smem-staged) =======================
__global__ void __launch_bounds__(256) prep_tok_frag(
    const int* __restrict__ seq, const float* __restrict__ embed)
{
    __shared__ float rows[16][516];
    int tm = blockIdx.x;
    int tid = threadIdx.x;
    int wid = tid >> 5, lane = tid & 31;

#pragma unroll
    for (int k = 0; k < 2; k++) {
        int rr = wid * 2 + k;
        int tok = seq[tm * 16 + rr];
        const float4* src = (const float4*)(embed + (size_t)tok * DD);
#pragma unroll
        for (int j = lane; j < 128; j += 32) {
            float4 v = src[j];
            float* d = &rows[rr][j * 4];
            d[0] = v.x; d[1] = v.y; d[2] = v.z; d[3] = v.w;
        }
    }
    __syncthreads();

    int r = lane >> 2, c = lane & 3;
#pragma unroll
    for (int it = 0; it < 8; it++) {
        int tk = it * 8 + wid;
        int kb = tk * 8 + c;
        float v0 = rows[r][kb];
        float v1 = rows[r + 8][kb];
        float v2 = rows[r][kb + 4];
        float v3 = rows[r + 8][kb + 4];
        float4 h, l;
        split2(v0, h.x, l.x); split2(v1, h.y, l.y);
        split2(v2, h.z, l.z); split2(v3, h.w, l.w);
        size_t slot = ((size_t)tm * 64 + tk) * 32 + lane;
        ((float4*)gAhi)[slot] = h;
        ((float4*)gAlo)[slot] = l;
    }
}

// ======================= prep: weights -> raw B fragments =======================
__global__ void __launch_bounds__(256) prep_w_frag(
    const float* __restrict__ W, int K8, int N, float* __restrict__ Bf)
{
    int slot = blockIdx.x * 256 + threadIdx.x;
    int lane = slot & 31;
    int tkn = slot >> 5;
    int tk = tkn % K8;
    int tn = tkn / K8;
    int k = tk * 8 + (lane & 3);
    int n = tn * 8 + (lane >> 2);
    float2 v;
    v.x = W[(size_t)k * N + n];
    v.y = W[(size_t)(k + 4) * N + n];
    ((float2*)Bf)[slot] = v;
}

// ======================= 3xTF32 mma GEMM: A pre-split, B otf trunc-split (R12) =============
#define OFF_AL    16384
#define OFF_B     32768
#define STAGE_SZ  49152
#define SMEM_REQ  (2 * STAGE_SZ)
#define CS_STRIDE 132

template<int KDIM, bool G1>
__global__ void __launch_bounds__(256, 2) mma_gemm(
    const float* __restrict__ Ahi, const float* __restrict__ Alo,
    const float* __restrict__ Bfrag,
    const float* __restrict__ bias,
    const int* __restrict__ seq, const float* __restrict__ embed,
    int mbase)
{
    extern __shared__ char smch[];
    const uint32_t smb = smem_u32(smch);
    const int tid = threadIdx.x;
    const int wid = tid >> 5;
    const int lane = tid & 31;
    const int warp_m = wid & 1;
    const int warp_n = wid >> 1;
    const int m0 = (mbase + blockIdx.y) * 128;
    const int n0 = blockIdx.x * 128;
    const int tm0 = m0 >> 4;
    const int tn0 = n0 >> 3;
    constexpr int AK8 = KDIM / 8;
    constexpr int NCH = KDIM / 32;

    float acc[4][4][4];
#pragma unroll
    for (int mt = 0; mt < 4; mt++)
#pragma unroll
        for (int nt = 0; nt < 4; nt++)
#pragma unroll
            for (int j = 0; j < 4; j++) acc[mt][nt][j] = 0.f;

    auto issue = [&](int ch) {
        int stage = ch & 1;
        uint32_t sb = smb + stage * STAGE_SZ;
        int tk0 = ch * 4;
#pragma unroll
        for (int it = 0; it < 4; it++) {
            int f = it * 256 + tid;
            int tm_l = f >> 7, tk_l = (f >> 5) & 3, ln = f & 31;
            size_t g4 = ((size_t)(tm0 + tm_l) * AK8 + tk0 + tk_l) * 32 + ln;
            cp16(sb + f * 16, Ahi + g4 * 4);
            cp16(sb + OFF_AL + f * 16, Alo + g4 * 4);
        }
#pragma unroll
        for (int it = 0; it < 4; it++) {
            int f = it * 256 + tid;
            int tn_l = f >> 6, tk_l = (f >> 4) & 3, lp = f & 15;
            size_t g4 = ((size_t)(tn0 + tn_l) * AK8 + tk0 + tk_l) * 16 + lp;
            cp16(sb + OFF_B + f * 16, Bfrag + g4 * 4);
        }
    };

    issue(0); CP_COMMIT();

    for (int i = 0; i < NCH; i++) {
        CP_WAIT(0);
        __syncthreads();
        if (i + 1 < NCH) { issue(i + 1); CP_COMMIT(); }

        int stage = i & 1;
        const uint4*  Ah = (const uint4*)(smch + stage * STAGE_SZ);
        const uint4*  Al = (const uint4*)(smch + stage * STAGE_SZ + OFF_AL);
        const float2* Bf = (const float2*)(smch + stage * STAGE_SZ + OFF_B);
#pragma unroll
        for (int kk = 0; kk < 4; kk++) {
            uint2 bh[4], bl[4];
#pragma unroll
            for (int nt = 0; nt < 4; nt++) {
                float2 b = Bf[((warp_n * 4 + nt) * 4 + kk) * 32 + lane];
                bh[nt].x = __float_as_uint(b.x);
                bh[nt].y = __float_as_uint(b.y);
                bl[nt].x = __float_as_uint(trunc_lo(b.x));
                bl[nt].y = __float_as_uint(trunc_lo(b.y));
            }
#pragma unroll
            for (int mt = 0; mt < 4; mt++) {
                int idx = ((warp_m * 4 + mt) * 4 + kk) * 32 + lane;
                uint4 ah = Ah[idx];
                uint4 al = Al[idx];
#pragma unroll
                for (int nt = 0; nt < 4; nt++) {
                    mma8(acc[mt][nt], ah, bh[nt]);
                    mma8(acc[mt][nt], ah, bl[nt]);
                    mma8(acc[mt][nt], al, bh[nt]);
                }
            }
        }
    }
    __syncthreads();

    // ---- epilogue via smem C tile ----
    float* Cs = (float*)smch;
    {
        int r0 = warp_m * 64 + (lane >> 2);
        int cb = warp_n * 32 + 2 * (lane & 3);
#pragma unroll
        for (int mt = 0; mt < 4; mt++)
#pragma unroll
            for (int nt = 0; nt < 4; nt++) {
                int row = r0 + mt * 16;
                int col = cb + nt * 8;
                Cs[row * CS_STRIDE + col]           = acc[mt][nt][0];
                Cs[row * CS_STRIDE + col + 1]       = acc[mt][nt][1];
                Cs[(row + 8) * CS_STRIDE + col]     = acc[mt][nt][2];
                Cs[(row + 8) * CS_STRIDE + col + 1] = acc[mt][nt][3];
            }
    }
    __syncthreads();

    if (G1) {
        for (int t = wid; t < 128; t += 8) {
            int tm = t >> 4, tkl = t & 15;
            float4 h4, l4;
            float* hp = &h4.x; float* lp = &l4.x;
#pragma unroll
            for (int q = 0; q < 4; q++) {
                int row = tm * 16 + (lane >> 2) + (q & 1) * 8;
                int col = tkl * 8 + (lane & 3) + (q >> 1) * 4;
                float v = Cs[row * CS_STRIDE + col] + bias[n0 + col];
                v = fmaxf(v, 0.f);
                hp[q] = v;
                lp[q] = trunc_lo(v);
            }
            size_t slot = ((size_t)(tm0 + tm) * 128 + (n0 >> 3) + tkl) * 32 + lane;
            ((float4*)gYhi)[slot] = h4;
            ((float4*)gYlo)[slot] = l4;
        }
    } else {
#pragma unroll
        for (int it = 0; it < 16; it++) {
            int f = it * 256 + tid;
            int row = f >> 5;
            int c4 = (f & 31) * 4;
            float4 v = *(float4*)(Cs + row * CS_STRIDE + c4);
            int grow = m0 + row;
            int gcol = n0 + c4;
            float4 e = *(const float4*)(embed + (size_t)seq[grow] * DD + gcol);
            v.x += bias[gcol] + e.x;
            v.y += bias[gcol + 1] + e.y;
            v.z += bias[gcol + 2] + e.z;
            v.w += bias[gcol + 3] + e.w;
            *(float4*)(g_X + (size_t)grow * DD + gcol) = v;
        }
    }
}

// ======================= LayerNorm scalars only (warp per row; no h store) ==================
__device__ __forceinline__ float warp_allred(float v) {
#pragma unroll
    for (int o = 16; o; o >>= 1) v += __shfl_xor_sync(0xffffffffu, v, o);
    return v;
}

__global__ void __launch_bounds__(256) ln_kernel(
    const float* __restrict__ lng, const float* __restrict__ lnb,
    const float* __restrict__ wgw, const float* __restrict__ wgb,
    const float* __restrict__ demw, const float* __restrict__ demb)
{
    int row = blockIdx.x * 8 + (threadIdx.x >> 5);
    int lane = threadIdx.x & 31;
    const float4* xr = (const float4*)(g_X + (size_t)row * DD);
    float4 x[4];
#pragma unroll
    for (int i = 0; i < 4; i++) x[i] = xr[lane + 32 * i];

    float s = 0.f;
#pragma unroll
    for (int i = 0; i < 4; i++) s += x[i].x + x[i].y + x[i].z + x[i].w;
    float mu = warp_allred(s) * (1.f / 512.f);

    float ss = 0.f;
#pragma unroll
    for (int i = 0; i < 4; i++) {
        float dx = x[i].x - mu, dy = x[i].y - mu, dz = x[i].z - mu, dw = x[i].w - mu;
        ss += dx * dx + dy * dy + dz * dz + dw * dw;
    }
    float var = warp_allred(ss) * (1.f / 512.f);
    float rstd = rsqrtf(var + 1e-5f);

    const float4* g4 = (const float4*)lng;
    const float4* b4 = (const float4*)lnb;
    const float4* w4 = (const float4*)wgw;
    const float4* d4 = (const float4*)demw;

    float wa = 0.f, da = 0.f;
#pragma unroll
    for (int i = 0; i < 4; i++) {
        float4 g = g4[lane + 32 * i], b = b4[lane + 32 * i];
        float4 w = w4[lane + 32 * i], dm = d4[lane + 32 * i];
        float4 h;
        h.x = (x[i].x - mu) * rstd * g.x + b.x;
        h.y = (x[i].y - mu) * rstd * g.y + b.y;
        h.z = (x[i].z - mu) * rstd * g.z + b.z;
        h.w = (x[i].w - mu) * rstd * g.w + b.w;
        wa += h.x * w.x + h.y * w.y + h.z * w.z + h.w * w.w;
        da += h.x * dm.x + h.y * dm.y + h.z * dm.z + h.w * dm.w;
    }
#pragma unroll
    for (int o = 16; o; o >>= 1) {
        wa += __shfl_xor_sync(0xffffffffu, wa, o);
        da += __shfl_xor_sync(0xffffffffu, da, o);
    }
    if (lane == 0) {
        g_ws[row] = wa + wgb[0];
        g_dm[row] = da + demb[0];
        g_mu[row] = mu;
        g_rs[row] = rstd;
    }
}

// ======================= q = ln(x_last) @ q_w + q_b (lazy LN) =======================
__global__ void __launch_bounds__(128) q_kernel(
    const float* __restrict__ qw, const float* __restrict__ qb,
    const float* __restrict__ lng, const float* __restrict__ lnb)
{
    int b = blockIdx.y, tid = threadIdx.x;
    int n = blockIdx.x * 128 + tid;
    int row = b * TT + TT - 1;
    __shared__ float hs[512];
    {
        float mu = g_mu[row], rs = g_rs[row];
        float4 x = *(const float4*)(g_X + (size_t)row * DD + tid * 4);
        float4 g = *(const float4*)(lng + tid * 4);
        float4 bb = *(const float4*)(lnb + tid * 4);
        float4 h;
        h.x = (x.x - mu) * rs * g.x + bb.x;
        h.y = (x.y - mu) * rs * g.y + bb.y;
        h.z = (x.z - mu) * rs * g.z + bb.z;
        h.w = (x.w - mu) * rs * g.w + bb.w;
        *(float4*)(hs + tid * 4) = h;
    }
    __syncthreads();
    float acc = 0.f;
#pragma unroll 16
    for (int k = 0; k < 512; k++) acc += hs[k] * qw[(size_t)k * 512 + n];
    g_q[b * DD + n] = acc + qb[n];
}

// ======================= fused scan + read head (lazy LN) =======================
__device__ __forceinline__ float blk128_max(float v, float* red) {
    int tid = threadIdx.x;
#pragma unroll
    for (int o = 16; o; o >>= 1) v = fmaxf(v, __shfl_xor_sync(0xffffffffu, v, o));
    __syncthreads();
    if ((tid & 31) == 0) red[tid >> 5] = v;
    __syncthreads();
    return fmaxf(fmaxf(red[0], red[1]), fmaxf(red[2], red[3]));
}
__device__ __forceinline__ float blk128_sum(float v, float* red) {
    int tid = threadIdx.x;
#pragma unroll
    for (int o = 16; o; o >>= 1) v += __shfl_xor_sync(0xffffffffu, v, o);
    __syncthreads();
    if ((tid & 31) == 0) red[tid >> 5] = v;
    __syncthreads();
    return red[0] + red[1] + red[2] + red[3];
}

__global__ void __launch_bounds__(128) readhead_kernel(
    const float* __restrict__ lng, const float* __restrict__ lnb)
{
    int b = blockIdx.x, tid = threadIdx.x;
    int wid = tid >> 5, lane = tid & 31;
    __shared__ float wss[256], dss[256];
    __shared__ float qs[512], gs[512], bs[512];
    __shared__ float attn[128], wn[128], mus[128], rss[128];
    __shared__ int   idx[128], rowarr[128];
    __shared__ float red[4];

    for (int t = tid; t < NSTEP; t += 128) {
        wss[t] = g_ws[b * TT + t];
        dss[t] = g_dm[b * TT + t];
    }
    for (int i = tid; i < 512; i += 128) {
        qs[i] = g_q[b * DD + i];
        gs[i] = lng[i];
        bs[i] = lnb[i];
    }
    __syncthreads();

    // ---- scan (warp 0 only) ----
    if (wid == 0) {
        int l = lane;
        int  ftok = -1;  bool fu = false;
        int  st0 = -1, st1 = -1, st2 = -1;
        int  sa0 = 0, sa1 = 0, sa2 = 0;
        bool su0 = false, su1 = false, su2 = false;

        for (int t = 0; t < NSTEP; t++) {
            float ws = 1.f / (1.f + expf(-wss[t]));
            bool write = (ws >= 0.4f);
            sa0 += su0; sa1 += su1; sa2 += su2;
            if (!write) continue;

            unsigned freeb = __ballot_sync(0xffffffffu, !fu);
            int target;
            if (freeb) {
                target = __ffs(freeb) - 1;
            } else {
                float bv = dss[ftok]; int bi = l;
#pragma unroll
                for (int o = 16; o; o >>= 1) {
                    float ov = __shfl_xor_sync(0xffffffffu, bv, o);
                    int   oi = __shfl_xor_sync(0xffffffffu, bi, o);
                    if (ov < bv || (ov == bv && oi < bi)) { bv = ov; bi = oi; }
                }
                target = bi;
                int dtok = __shfl_sync(0xffffffffu, ftok, target);

                unsigned f0 = __ballot_sync(0xffffffffu, !su0);
                unsigned f1 = __ballot_sync(0xffffffffu, !su1);
                unsigned f2 = __ballot_sync(0xffffffffu, !su2);
                int ss;
                if (f0)      ss = __ffs(f0) - 1;
                else if (f1) ss = 32 + __ffs(f1) - 1;
                else if (f2) ss = 64 + __ffs(f2) - 1;
                else {
                    int mv = sa0, mi = l;
                    if (sa1 > mv) { mv = sa1; mi = 32 + l; }
                    if (sa2 > mv) { mv = sa2; mi = 64 + l; }
#pragma unroll
                    for (int o = 16; o; o >>= 1) {
                        int ov = __shfl_xor_sync(0xffffffffu, mv, o);
                        int oi = __shfl_xor_sync(0xffffffffu, mi, o);
                        if (ov > mv || (ov == mv && oi < mi)) { mv = ov; mi = oi; }
                    }
                    ss = mi;
                }
                int g = ss >> 5, ol = ss & 31;
                if (l == ol) {
                    if (g == 0)      { st0 = dtok; sa0 = 0; su0 = true; }
                    else if (g == 1) { st1 = dtok; sa1 = 0; su1 = true; }
                    else             { st2 = dtok; sa2 = 0; su2 = true; }
                }
            }
            if (l == target) { ftok = t; fu = true; }
        }
        idx[l]      = fu  ? ftok : -1;
        idx[32 + l] = su0 ? st0  : -1;
        idx[64 + l] = su1 ? st1  : -1;
        idx[96 + l] = su2 ? st2  : -1;
    }
    __syncthreads();

    // per-slot row + LN scalars
    {
        int tok = idx[tid];
        int row = b * TT + (tok >= 0 ? tok : 0);
        rowarr[tid] = row;
        mus[tid] = g_mu[row];
        rss[tid] = g_rs[row];
    }
    __syncthreads();

    // ---- scores: each warp computes 32 slots; lazy LN from g_X ----
    float qreg[16];
    {
        const float4* q4 = (const float4*)(qs + lane * 16);
#pragma unroll
        for (int j = 0; j < 4; j++) {
            float4 v = q4[j];
            qreg[j * 4] = v.x; qreg[j * 4 + 1] = v.y; qreg[j * 4 + 2] = v.z; qreg[j * 4 + 3] = v.w;
        }
    }
    float greg[16], breg[16];
    {
        const float4* gg = (const float4*)(gs + lane * 16);
        const float4* bb = (const float4*)(bs + lane * 16);
#pragma unroll
        for (int j = 0; j < 4; j++) {
            float4 g = gg[j], b2 = bb[j];
            greg[j * 4] = g.x; greg[j * 4 + 1] = g.y; greg[j * 4 + 2] = g.z; greg[j * 4 + 3] = g.w;
            breg[j * 4] = b2.x; breg[j * 4 + 1] = b2.y; breg[j * 4 + 2] = b2.z; breg[j * 4 + 3] = b2.w;
        }
    }
    float myscore = -1e9f;
    for (int s32 = 0; s32 < 32; s32++) {
        int slot = wid * 32 + s32;
        int tok = idx[slot];
        int row = rowarr[slot];
        float mu = mus[slot], rs = rss[slot];
        const float4* m4 = (const float4*)(g_X + (size_t)row * DD + lane * 16);
        float acc = 0.f;
#pragma unroll
        for (int j = 0; j < 4; j++) {
            float4 v = m4[j];
#pragma unroll
            for (int e = 0; e < 4; e++) {
                float xv = (&v.x)[e];
                float h = (xv - mu) * rs * greg[j * 4 + e] + breg[j * 4 + e];
                acc += h * qreg[j * 4 + e];
            }
        }
        acc = warp_allred(acc);
        if (lane == s32) myscore = (tok >= 0) ? acc : -1e9f;
    }

    // ---- softmax over 128 slots ----
    float mx = blk128_max(myscore, red);
    __syncthreads();
    float e = expf(myscore - mx);
    float denom = blk128_sum(e, red);
    float at = e / denom;
    attn[tid] = at;
    wn[tid] = at * rss[tid];       // attn * rstd (0 for invalid slots)
    __syncthreads();

    // S0 = sum attn, S1 = sum wn*mu
    float S0 = 0.f, S1 = 0.f;
#pragma unroll 16
    for (int n2 = 0; n2 < 128; n2++) {
        S0 += attn[n2];
        S1 += wn[n2] * mus[n2];
    }

    // ---- ctx: ctx_d = g_d*(sum_n wn_n * x[row_n][d] - S1) + b_d*S0 ----
    for (int d = tid; d < 512; d += 128) {
        float acc = 0.f;
#pragma unroll 8
        for (int n2 = 0; n2 < 128; n2++) {
            acc += wn[n2] * g_X[(size_t)rowarr[n2] * DD + d];
        }
        g_ctxT[d * BB + b] = gs[d] * (acc - S1) + bs[d] * S0;
    }
}

// ======================= logits = ctx @ out_w + out_b =======================
__global__ void __launch_bounds__(128) out_kernel(
    const float* __restrict__ outw, const float* __restrict__ outb,
    float* __restrict__ out)
{
    __shared__ __align__(16) float cst[512 * 16];
    int vblk = blockIdx.x >> 1;
    int bh = blockIdx.x & 1;
    int tid = threadIdx.x;
    int v0 = vblk * 256 + tid * 2;

    {
        const float4* src = (const float4*)g_ctxT;
        float4* dst = (float4*)cst;
#pragma unroll
        for (int it = 0; it < 16; it++) {
            int f = it * 128 + tid;
            int d = f >> 2;
            int j4 = f & 3;
            dst[d * 4 + j4] = src[d * 8 + bh * 4 + j4];
        }
    }
    __syncthreads();

    u64 acc0[8], acc1[8];
#pragma unroll
    for (int j = 0; j < 8; j++) { acc0[j] = 0ull; acc1[j] = 0ull; }

#pragma unroll 16
    for (int dl = 0; dl < 512; dl++) {
        float2 w = *(const float2*)(outw + (size_t)dl * VV + v0);
        u64 w2x = pack_dup(w.x);
        u64 w2y = pack_dup(w.y);
        const u64* cp = (const u64*)(cst + dl * 16);
#pragma unroll
        for (int j = 0; j < 8; j++) {
            u64 c = cp[j];
            acc0[j] = ffma2(w2x, c, acc0[j]);
            acc1[j] = ffma2(w2y, c, acc1[j]);
        }
    }

    float ob0 = outb[v0], ob1 = outb[v0 + 1];
#pragma unroll
    for (int j = 0; j < 8; j++) {
        float a0l, a0h, a1l, a1h;
        unpack2(acc0[j], a0l, a0h);
        unpack2(acc1[j], a1l, a1h);
        int brow = bh * 16 + 2 * j;
        float2 o0; o0.x = a0l + ob0; o0.y = a1l + ob1;
        float2 o1; o1.x = a0h + ob0; o1.y = a1h + ob1;
        *(float2*)(out + (size_t)brow * VV + v0)       = o0;
        *(float2*)(out + (size_t)(brow + 1) * VV + v0) = o1;
    }
}

// ======================= launch =======================
extern "C" void kernel_launch(void* const* d_in, const int* in_sizes, int n_in,
                              void* d_out, int out_size)
{
    const int*   seq   = (const int*)d_in[0];
    const float* embed = (const float*)d_in[1];
    const float* ff1w  = (const float*)d_in[2];
    const float* ff1b  = (const float*)d_in[3];
    const float* ff2w  = (const float*)d_in[4];
    const float* ff2b  = (const float*)d_in[5];
    const float* lng   = (const float*)d_in[6];
    const float* lnb   = (const float*)d_in[7];
    const float* wgw   = (const float*)d_in[8];
    const float* wgb   = (const float*)d_in[9];
    const float* demw  = (const float*)d_in[10];
    const float* demb  = (const float*)d_in[11];
    const float* qw    = (const float*)d_in[12];
    const float* qb    = (const float*)d_in[13];
    const float* outw  = (const float*)d_in[14];
    const float* outb  = (const float*)d_in[15];
    float* out = (float*)d_out;

    float *pAhi, *pAlo, *pYhi, *pYlo, *pW1, *pW2;
    cudaGetSymbolAddress((void**)&pAhi, gAhi);
    cudaGetSymbolAddress((void**)&pAlo, gAlo);
    cudaGetSymbolAddress((void**)&pYhi, gYhi);
    cudaGetSymbolAddress((void**)&pYlo, gYlo);
    cudaGetSymbolAddress((void**)&pW1, gW1);
    cudaGetSymbolAddress((void**)&pW2, gW2);

    static bool init_done = false;
    static cudaStream_t s1;
    static cudaEvent_t evA, evB, evC;
    if (!init_done) {
        cudaFuncSetAttribute(mma_gemm<512, true>,   cudaFuncAttributeMaxDynamicSharedMemorySize, SMEM_REQ);
        cudaFuncSetAttribute(mma_gemm<1024, false>, cudaFuncAttributeMaxDynamicSharedMemorySize, SMEM_REQ);
        cudaStreamCreateWithFlags(&s1, cudaStreamNonBlocking);
        cudaEventCreateWithFlags(&evA, cudaEventDisableTiming);
        cudaEventCreateWithFlags(&evB, cudaEventDisableTiming);
        cudaEventCreateWithFlags(&evC, cudaEventDisableTiming);
        init_done = true;
    }

    prep_tok_frag<<<MR / 16, 256>>>(seq, embed);
    prep_w_frag<<<(1024 / 8) * (512 / 8) * 32 / 256, 256>>>(ff1w, 512 / 8, 1024, pW1);
    prep_w_frag<<<(512 / 8) * (1024 / 8) * 32 / 256, 256>>>(ff2w, 1024 / 8, 512, pW2);

    // gemm1 half A (token rows 0..4095)
    mma_gemm<512, true><<<dim3(8, 32), 256, SMEM_REQ>>>(
        pAhi, pAlo, pW1, ff1b, seq, embed, 0);
    cudaEventRecord(evA, 0);
    // gemm1 half B (token rows 4096..8191) — overlaps gemm2 half A on s1
    mma_gemm<512, true><<<dim3(8, 32), 256, SMEM_REQ>>>(
        pAhi, pAlo, pW1, ff1b, seq, embed, 32);
    cudaEventRecord(evB, 0);

    cudaStreamWaitEvent(s1, evA, 0);
    mma_gemm<1024, false><<<dim3(4, 32), 256, SMEM_REQ, s1>>>(
        pYhi, pYlo, pW2, ff2b, seq, embed, 0);
    cudaStreamWaitEvent(s1, evB, 0);
    mma_gemm<1024, false><<<dim3(4, 32), 256, SMEM_REQ, s1>>>(
        pYhi, pYlo, pW2, ff2b, seq, embed, 32);
    cudaEventRecord(evC, s1);

    cudaStreamWaitEvent(0, evC, 0);
    ln_kernel<<<MR / 8, 256>>>(lng, lnb, wgw, wgb, demw, demb);
    q_kernel<<<dim3(4, BB), 128>>>(qw, qb, lng, lnb);
    readhead_kernel<<<BB, 128>>>(lng, lnb);
    out_kernel<<<250, 128>>>(outw, outb, out);
}

// round 17
// speedup vs baseline: 1.1109x; 1.1109x over previous
#include <cuda_runtime.h>
#include <math.h>
#include <stdint.h>

typedef unsigned long long u64;

#define BB 32
#define TT 256
#define DD 512
#define VV 32000
#define MR (BB*TT)        // 8192 token rows
#define NSTEP (TT-3)      // 253 scan steps

// ======================= device scratch (fragment-ordered operands) =======================
__device__ __align__(256) float gAhi[MR * DD];
__device__ __align__(256) float gAlo[MR * DD];
__device__ __align__(256) float gYhi[MR * 1024];
__device__ __align__(256) float gYlo[MR * 1024];
__device__ __align__(256) float gW1[1024 * 512];
__device__ __align__(256) float gW2[512 * 1024];
__device__ float g_X[MR * DD];        // pre-LN residual (fp32)
__device__ float g_mu[MR];            // LN mean per row
__device__ float g_rs[MR];            // LN rstd per row
__device__ float g_ws[MR];
__device__ float g_dm[MR];
__device__ float g_q[BB * DD];
__device__ float g_ctxT[DD * BB];

// ======================= helpers =======================
__device__ __forceinline__ float to_tf32(float x) {
    float r; asm("cvt.rna.tf32.f32 %0, %1;" : "=f"(r) : "f"(x)); return r;
}
__device__ __forceinline__ void split2(float v, float& hi, float& lo) {
    hi = to_tf32(v);
    lo = v - hi;
}
__device__ __forceinline__ float trunc_lo(float v) {
    uint32_t m = __float_as_uint(v) & 0xFFFFE000u;
    return v - __uint_as_float(m);
}
__device__ __forceinline__ uint32_t smem_u32(const void* p) {
    uint32_t a;
    asm("{ .reg .u64 t; cvta.to.shared.u64 t, %1; cvt.u32.u64 %0, t; }" : "=r"(a) : "l"(p));
    return a;
}
__device__ __forceinline__ void cp16(uint32_t dst, const void* src) {
    asm volatile("cp.async.cg.shared.global [%0], [%1], 16;" :: "r"(dst), "l"(src));
}
#define CP_COMMIT() asm volatile("cp.async.commit_group;" ::: "memory")
#define CP_WAIT(n)  asm volatile("cp.async.wait_group %0;" :: "n"(n) : "memory")

__device__ __forceinline__ void mma8(float* c, uint4 a, uint2 b) {
    asm volatile(
        "mma.sync.aligned.m16n8k8.row.col.f32.tf32.tf32.f32 "
        "{%0,%1,%2,%3}, {%4,%5,%6,%7}, {%8,%9}, {%0,%1,%2,%3};"
        : "+f"(c[0]), "+f"(c[1]), "+f"(c[2]), "+f"(c[3])
        : "r"(a.x), "r"(a.y), "r"(a.z), "r"(a.w), "r"(b.x), "r"(b.y));
}

__device__ __forceinline__ u64 pack_dup(float x) {
    u64 r; asm("mov.b64 %0, {%1, %1};" : "=l"(r) : "f"(x)); return r;
}
__device__ __forceinline__ u64 ffma2(u64 a, u64 b, u64 c) {
    u64 d; asm("fma.rn.f32x2 %0, %1, %2, %3;" : "=l"(d) : "l"(a), "l"(b), "l"(c)); return d;
}
__device__ __forceinline__ void unpack2(u64 v, float& lo, float& hi) {
    asm("mov.b64 {%0, %1}, %2;" : "=f"(lo), "=f"(hi) : "l"(v));
}

// ======================= prep: tokens -> split A fragments (smem-staged) =======================
__global__ void __launch_bounds__(256) prep_tok_frag(
    const int* __restrict__ seq, const float* __restrict__ embed)
{
    __shared__ float rows[16][516];
    int tm = blockIdx.x;
    int tid = threadIdx.x;
    int wid = tid >> 5, lane = tid & 31;

#pragma unroll
    for (int k = 0; k < 2; k++) {
        int rr = wid * 2 + k;
        int tok = seq[tm * 16 + rr];
        const float4* src = (const float4*)(embed + (size_t)tok * DD);
#pragma unroll
        for (int j = lane; j < 128; j += 32) {
            float4 v = src[j];
            float* d = &rows[rr][j * 4];
            d[0] = v.x; d[1] = v.y; d[2] = v.z; d[3] = v.w;
        }
    }
    __syncthreads();

    int r = lane >> 2, c = lane & 3;
#pragma unroll
    for (int it = 0; it < 8; it++) {
        int tk = it * 8 + wid;
        int kb = tk * 8 + c;
        float v0 = rows[r][kb];
        float v1 = rows[r + 8][kb];
        float v2 = rows[r][kb + 4];
        float v3 = rows[r + 8][kb + 4];
        float4 h, l;
        split2(v0, h.x, l.x); split2(v1, h.y, l.y);
        split2(v2, h.z, l.z); split2(v3, h.w, l.w);
        size_t slot = ((size_t)tm * 64 + tk) * 32 + lane;
        ((float4*)gAhi)[slot] = h;
        ((float4*)gAlo)[slot] = l;
    }
}

// ======================= prep: weights -> raw B fragments =======================
__global__ void __launch_bounds__(256) prep_w_frag(
    const float* __restrict__ W, int K8, int N, float* __restrict__ Bf)
{
    int slot = blockIdx.x * 256 + threadIdx.x;
    int lane = slot & 31;
    int tkn = slot >> 5;
    int tk = tkn % K8;
    int tn = tkn / K8;
    int k = tk * 8 + (lane & 3);
    int n = tn * 8 + (lane >> 2);
    float2 v;
    v.x = W[(size_t)k * N + n];
    v.y = W[(size_t)(k + 4) * N + n];
    ((float2*)Bf)[slot] = v;
}

// ======================= 3xTF32 mma GEMM: A pre-split, B otf trunc-split (R12) =============
#define OFF_AL    16384
#define OFF_B     32768
#define STAGE_SZ  49152
#define SMEM_REQ  (2 * STAGE_SZ)
#define CS_STRIDE 132

template<int KDIM, bool G1>
__global__ void __launch_bounds__(256, 2) mma_gemm(
    const float* __restrict__ Ahi, const float* __restrict__ Alo,
    const float* __restrict__ Bfrag,
    const float* __restrict__ bias,
    const int* __restrict__ seq, const float* __restrict__ embed)
{
    extern __shared__ char smch[];
    const uint32_t smb = smem_u32(smch);
    const int tid = threadIdx.x;
    const int wid = tid >> 5;
    const int lane = tid & 31;
    const int warp_m = wid & 1;
    const int warp_n = wid >> 1;
    const int m0 = blockIdx.y * 128;
    const int n0 = blockIdx.x * 128;
    const int tm0 = m0 >> 4;
    const int tn0 = n0 >> 3;
    constexpr int AK8 = KDIM / 8;
    constexpr int NCH = KDIM / 32;

    float acc[4][4][4];
#pragma unroll
    for (int mt = 0; mt < 4; mt++)
#pragma unroll
        for (int nt = 0; nt < 4; nt++)
#pragma unroll
            for (int j = 0; j < 4; j++) acc[mt][nt][j] = 0.f;

    auto issue = [&](int ch) {
        int stage = ch & 1;
        uint32_t sb = smb + stage * STAGE_SZ;
        int tk0 = ch * 4;
#pragma unroll
        for (int it = 0; it < 4; it++) {
            int f = it * 256 + tid;
            int tm_l = f >> 7, tk_l = (f >> 5) & 3, ln = f & 31;
            size_t g4 = ((size_t)(tm0 + tm_l) * AK8 + tk0 + tk_l) * 32 + ln;
            cp16(sb + f * 16, Ahi + g4 * 4);
            cp16(sb + OFF_AL + f * 16, Alo + g4 * 4);
        }
#pragma unroll
        for (int it = 0; it < 4; it++) {
            int f = it * 256 + tid;
            int tn_l = f >> 6, tk_l = (f >> 4) & 3, lp = f & 15;
            size_t g4 = ((size_t)(tn0 + tn_l) * AK8 + tk0 + tk_l) * 16 + lp;
            cp16(sb + OFF_B + f * 16, Bfrag + g4 * 4);
        }
    };

    issue(0); CP_COMMIT();

    for (int i = 0; i < NCH; i++) {
        CP_WAIT(0);
        __syncthreads();
        if (i + 1 < NCH) { issue(i + 1); CP_COMMIT(); }

        int stage = i & 1;
        const uint4*  Ah = (const uint4*)(smch + stage * STAGE_SZ);
        const uint4*  Al = (const uint4*)(smch + stage * STAGE_SZ + OFF_AL);
        const float2* Bf = (const float2*)(smch + stage * STAGE_SZ + OFF_B);
#pragma unroll
        for (int kk = 0; kk < 4; kk++) {
            uint2 bh[4], bl[4];
#pragma unroll
            for (int nt = 0; nt < 4; nt++) {
                float2 b = Bf[((warp_n * 4 + nt) * 4 + kk) * 32 + lane];
                bh[nt].x = __float_as_uint(b.x);
                bh[nt].y = __float_as_uint(b.y);
                bl[nt].x = __float_as_uint(trunc_lo(b.x));
                bl[nt].y = __float_as_uint(trunc_lo(b.y));
            }
#pragma unroll
            for (int mt = 0; mt < 4; mt++) {
                int idx = ((warp_m * 4 + mt) * 4 + kk) * 32 + lane;
                uint4 ah = Ah[idx];
                uint4 al = Al[idx];
#pragma unroll
                for (int nt = 0; nt < 4; nt++) {
                    mma8(acc[mt][nt], ah, bh[nt]);
                    mma8(acc[mt][nt], ah, bl[nt]);
                    mma8(acc[mt][nt], al, bh[nt]);
                }
            }
        }
    }
    __syncthreads();

    // ---- epilogue via smem C tile ----
    float* Cs = (float*)smch;
    {
        int r0 = warp_m * 64 + (lane >> 2);
        int cb = warp_n * 32 + 2 * (lane & 3);
#pragma unroll
        for (int mt = 0; mt < 4; mt++)
#pragma unroll
            for (int nt = 0; nt < 4; nt++) {
                int row = r0 + mt * 16;
                int col = cb + nt * 8;
                Cs[row * CS_STRIDE + col]           = acc[mt][nt][0];
                Cs[row * CS_STRIDE + col + 1]       = acc[mt][nt][1];
                Cs[(row + 8) * CS_STRIDE + col]     = acc[mt][nt][2];
                Cs[(row + 8) * CS_STRIDE + col + 1] = acc[mt][nt][3];
            }
    }
    __syncthreads();

    if (G1) {
        for (int t = wid; t < 128; t += 8) {
            int tm = t >> 4, tkl = t & 15;
            float4 h4, l4;
            float* hp = &h4.x; float* lp = &l4.x;
#pragma unroll
            for (int q = 0; q < 4; q++) {
                int row = tm * 16 + (lane >> 2) + (q & 1) * 8;
                int col = tkl * 8 + (lane & 3) + (q >> 1) * 4;
                float v = Cs[row * CS_STRIDE + col] + bias[n0 + col];
                v = fmaxf(v, 0.f);
                hp[q] = v;
                lp[q] = trunc_lo(v);
            }
            size_t slot = ((size_t)(tm0 + tm) * 128 + (n0 >> 3) + tkl) * 32 + lane;
            ((float4*)gYhi)[slot] = h4;
            ((float4*)gYlo)[slot] = l4;
        }
    } else {
#pragma unroll
        for (int it = 0; it < 16; it++) {
            int f = it * 256 + tid;
            int row = f >> 5;
            int c4 = (f & 31) * 4;
            float4 v = *(float4*)(Cs + row * CS_STRIDE + c4);
            int grow = m0 + row;
            int gcol = n0 + c4;
            float4 e = *(const float4*)(embed + (size_t)seq[grow] * DD + gcol);
            v.x += bias[gcol] + e.x;
            v.y += bias[gcol + 1] + e.y;
            v.z += bias[gcol + 2] + e.z;
            v.w += bias[gcol + 3] + e.w;
            *(float4*)(g_X + (size_t)grow * DD + gcol) = v;
        }
    }
}

// ======================= LayerNorm scalars only (warp per row; no h store) ==================
__device__ __forceinline__ float warp_allred(float v) {
#pragma unroll
    for (int o = 16; o; o >>= 1) v += __shfl_xor_sync(0xffffffffu, v, o);
    return v;
}

__global__ void __launch_bounds__(256) ln_kernel(
    const float* __restrict__ lng, const float* __restrict__ lnb,
    const float* __restrict__ wgw, const float* __restrict__ wgb,
    const float* __restrict__ demw, const float* __restrict__ demb)
{
    int row = blockIdx.x * 8 + (threadIdx.x >> 5);
    int lane = threadIdx.x & 31;
    const float4* xr = (const float4*)(g_X + (size_t)row * DD);
    float4 x[4];
#pragma unroll
    for (int i = 0; i < 4; i++) x[i] = xr[lane + 32 * i];

    float s = 0.f;
#pragma unroll
    for (int i = 0; i < 4; i++) s += x[i].x + x[i].y + x[i].z + x[i].w;
    float mu = warp_allred(s) * (1.f / 512.f);

    float ss = 0.f;
#pragma unroll
    for (int i = 0; i < 4; i++) {
        float dx = x[i].x - mu, dy = x[i].y - mu, dz = x[i].z - mu, dw = x[i].w - mu;
        ss += dx * dx + dy * dy + dz * dz + dw * dw;
    }
    float var = warp_allred(ss) * (1.f / 512.f);
    float rstd = rsqrtf(var + 1e-5f);

    const float4* g4 = (const float4*)lng;
    const float4* b4 = (const float4*)lnb;
    const float4* w4 = (const float4*)wgw;
    const float4* d4 = (const float4*)demw;

    float wa = 0.f, da = 0.f;
#pragma unroll
    for (int i = 0; i < 4; i++) {
        float4 g = g4[lane + 32 * i], b = b4[lane + 32 * i];
        float4 w = w4[lane + 32 * i], dm = d4[lane + 32 * i];
        float4 h;
        h.x = (x[i].x - mu) * rstd * g.x + b.x;
        h.y = (x[i].y - mu) * rstd * g.y + b.y;
        h.z = (x[i].z - mu) * rstd * g.z + b.z;
        h.w = (x[i].w - mu) * rstd * g.w + b.w;
        wa += h.x * w.x + h.y * w.y + h.z * w.z + h.w * w.w;
        da += h.x * dm.x + h.y * dm.y + h.z * dm.z + h.w * dm.w;
    }
#pragma unroll
    for (int o = 16; o; o >>= 1) {
        wa += __shfl_xor_sync(0xffffffffu, wa, o);
        da += __shfl_xor_sync(0xffffffffu, da, o);
    }
    if (lane == 0) {
        g_ws[row] = wa + wgb[0];
        g_dm[row] = da + demb[0];
        g_mu[row] = mu;
        g_rs[row] = rstd;
    }
}

// ======================= q = ln(x_last) @ q_w + q_b (lazy LN) =======================
__global__ void __launch_bounds__(128) q_kernel(
    const float* __restrict__ qw, const float* __restrict__ qb,
    const float* __restrict__ lng, const float* __restrict__ lnb)
{
    int b = blockIdx.y, tid = threadIdx.x;
    int n = blockIdx.x * 128 + tid;
    int row = b * TT + TT - 1;
    __shared__ float hs[512];
    {
        float mu = g_mu[row], rs = g_rs[row];
        float4 x = *(const float4*)(g_X + (size_t)row * DD + tid * 4);
        float4 g = *(const float4*)(lng + tid * 4);
        float4 bb = *(const float4*)(lnb + tid * 4);
        float4 h;
        h.x = (x.x - mu) * rs * g.x + bb.x;
        h.y = (x.y - mu) * rs * g.y + bb.y;
        h.z = (x.z - mu) * rs * g.z + bb.z;
        h.w = (x.w - mu) * rs * g.w + bb.w;
        *(float4*)(hs + tid * 4) = h;
    }
    __syncthreads();
    float acc = 0.f;
#pragma unroll 16
    for (int k = 0; k < 512; k++) acc += hs[k] * qw[(size_t)k * 512 + n];
    g_q[b * DD + n] = acc + qb[n];
}

// ======================= fused scan + read head (lazy LN, 256 threads) =======================
__device__ __forceinline__ float blk256_max(float v, float* red) {
    int tid = threadIdx.x;
#pragma unroll
    for (int o = 16; o; o >>= 1) v = fmaxf(v, __shfl_xor_sync(0xffffffffu, v, o));
    if ((tid & 31) == 0) red[tid >> 5] = v;
    __syncthreads();
    float m = red[0];
#pragma unroll
    for (int i = 1; i < 8; i++) m = fmaxf(m, red[i]);
    __syncthreads();
    return m;
}
__device__ __forceinline__ float blk256_sum(float v, float* red) {
    int tid = threadIdx.x;
#pragma unroll
    for (int o = 16; o; o >>= 1) v += __shfl_xor_sync(0xffffffffu, v, o);
    if ((tid & 31) == 0) red[tid >> 5] = v;
    __syncthreads();
    float s = 0.f;
#pragma unroll
    for (int i = 0; i < 8; i++) s += red[i];
    __syncthreads();
    return s;
}

__global__ void __launch_bounds__(256) readhead_kernel(
    const float* __restrict__ lng, const float* __restrict__ lnb)
{
    int b = blockIdx.x, tid = threadIdx.x;
    int wid = tid >> 5, lane = tid & 31;
    __shared__ float wss[256], dss[256];
    __shared__ float qs[512], gs[512], bs[512];
    __shared__ float scr[128], attn[128], wn[128], mus[128], rss[128];
    __shared__ int   idx[128], rowarr[128];
    __shared__ float red[8];

    for (int t = tid; t < NSTEP; t += 256) {
        wss[t] = g_ws[b * TT + t];
        dss[t] = g_dm[b * TT + t];
    }
    for (int i = tid; i < 512; i += 256) {
        qs[i] = g_q[b * DD + i];
        gs[i] = lng[i];
        bs[i] = lnb[i];
    }
    __syncthreads();

    // ---- scan (warp 0 only) ----
    if (wid == 0) {
        int l = lane;
        int  ftok = -1;  bool fu = false;
        int  st0 = -1, st1 = -1, st2 = -1;
        int  sa0 = 0, sa1 = 0, sa2 = 0;
        bool su0 = false, su1 = false, su2 = false;

        for (int t = 0; t < NSTEP; t++) {
            float ws = 1.f / (1.f + expf(-wss[t]));
            bool write = (ws >= 0.4f);
            sa0 += su0; sa1 += su1; sa2 += su2;
            if (!write) continue;

            unsigned freeb = __ballot_sync(0xffffffffu, !fu);
            int target;
            if (freeb) {
                target = __ffs(freeb) - 1;
            } else {
                float bv = dss[ftok]; int bi = l;
#pragma unroll
                for (int o = 16; o; o >>= 1) {
                    float ov = __shfl_xor_sync(0xffffffffu, bv, o);
                    int   oi = __shfl_xor_sync(0xffffffffu, bi, o);
                    if (ov < bv || (ov == bv && oi < bi)) { bv = ov; bi = oi; }
                }
                target = bi;
                int dtok = __shfl_sync(0xffffffffu, ftok, target);

                unsigned f0 = __ballot_sync(0xffffffffu, !su0);
                unsigned f1 = __ballot_sync(0xffffffffu, !su1);
                unsigned f2 = __ballot_sync(0xffffffffu, !su2);
                int ss;
                if (f0)      ss = __ffs(f0) - 1;
                else if (f1) ss = 32 + __ffs(f1) - 1;
                else if (f2) ss = 64 + __ffs(f2) - 1;
                else {
                    int mv = sa0, mi = l;
                    if (sa1 > mv) { mv = sa1; mi = 32 + l; }
                    if (sa2 > mv) { mv = sa2; mi = 64 + l; }
#pragma unroll
                    for (int o = 16; o; o >>= 1) {
                        int ov = __shfl_xor_sync(0xffffffffu, mv, o);
                        int oi = __shfl_xor_sync(0xffffffffu, mi, o);
                        if (ov > mv || (ov == mv && oi < mi)) { mv = ov; mi = oi; }
                    }
                    ss = mi;
                }
                int g = ss >> 5, ol = ss & 31;
                if (l == ol) {
                    if (g == 0)      { st0 = dtok; sa0 = 0; su0 = true; }
                    else if (g == 1) { st1 = dtok; sa1 = 0; su1 = true; }
                    else             { st2 = dtok; sa2 = 0; su2 = true; }
                }
            }
            if (l == target) { ftok = t; fu = true; }
        }
        idx[l]      = fu  ? ftok : -1;
        idx[32 + l] = su0 ? st0  : -1;
        idx[64 + l] = su1 ? st1  : -1;
        idx[96 + l] = su2 ? st2  : -1;
    }
    __syncthreads();

    // per-slot row + LN scalars
    if (tid < 128) {
        int tok = idx[tid];
        int row = b * TT + (tok >= 0 ? tok : 0);
        rowarr[tid] = row;
        mus[tid] = g_mu[row];
        rss[tid] = g_rs[row];
    }
    __syncthreads();

    // ---- scores: each warp computes 16 slots; lazy LN from g_X ----
    float qreg[16];
    {
        const float4* q4 = (const float4*)(qs + lane * 16);
#pragma unroll
        for (int j = 0; j < 4; j++) {
            float4 v = q4[j];
            qreg[j * 4] = v.x; qreg[j * 4 + 1] = v.y; qreg[j * 4 + 2] = v.z; qreg[j * 4 + 3] = v.w;
        }
    }
    float greg[16], breg[16];
    {
        const float4* gg = (const float4*)(gs + lane * 16);
        const float4* bb = (const float4*)(bs + lane * 16);
#pragma unroll
        for (int j = 0; j < 4; j++) {
            float4 g = gg[j], b2 = bb[j];
            greg[j * 4] = g.x; greg[j * 4 + 1] = g.y; greg[j * 4 + 2] = g.z; greg[j * 4 + 3] = g.w;
            breg[j * 4] = b2.x; breg[j * 4 + 1] = b2.y; breg[j * 4 + 2] = b2.z; breg[j * 4 + 3] = b2.w;
        }
    }
    for (int s16 = 0; s16 < 16; s16++) {
        int slot = wid * 16 + s16;
        int tok = idx[slot];
        int row = rowarr[slot];
        float mu = mus[slot], rs = rss[slot];
        const float4* m4 = (const float4*)(g_X + (size_t)row * DD + lane * 16);
        float acc = 0.f;
#pragma unroll
        for (int j = 0; j < 4; j++) {
            float4 v = m4[j];
#pragma unroll
            for (int e = 0; e < 4; e++) {
                float xv = (&v.x)[e];
                float h = (xv - mu) * rs * greg[j * 4 + e] + breg[j * 4 + e];
                acc += h * qreg[j * 4 + e];
            }
        }
        acc = warp_allred(acc);
        if (lane == s16) scr[slot] = (tok >= 0) ? acc : -1e9f;
    }
    __syncthreads();

    // ---- softmax over 128 slots (256-thread reductions) ----
    float myscore = (tid < 128) ? scr[tid] : -1e30f;
    float mx = blk256_max(myscore, red);
    float e = (tid < 128) ? expf(myscore - mx) : 0.f;
    float denom = blk256_sum(e, red);
    if (tid < 128) {
        float at = e / denom;
        attn[tid] = at;
        wn[tid] = at * rss[tid];   // attn * rstd (0 for invalid slots)
    }
    __syncthreads();

    // S0 = sum attn, S1 = sum wn*mu
    float S0 = 0.f, S1 = 0.f;
#pragma unroll 16
    for (int n2 = 0; n2 < 128; n2++) {
        S0 += attn[n2];
        S1 += wn[n2] * mus[n2];
    }

    // ---- ctx: ctx_d = g_d*(sum_n wn_n * x[row_n][d] - S1) + b_d*S0 ----
    for (int d = tid; d < 512; d += 256) {
        float acc = 0.f;
#pragma unroll 8
        for (int n2 = 0; n2 < 128; n2++) {
            acc += wn[n2] * g_X[(size_t)rowarr[n2] * DD + d];
        }
        g_ctxT[d * BB + b] = gs[d] * (acc - S1) + bs[d] * S0;
    }
}

// ======================= logits = ctx @ out_w + out_b =======================
__global__ void __launch_bounds__(128) out_kernel(
    const float* __restrict__ outw, const float* __restrict__ outb,
    float* __restrict__ out)
{
    __shared__ __align__(16) float cst[512 * 16];
    int vblk = blockIdx.x >> 1;
    int bh = blockIdx.x & 1;
    int tid = threadIdx.x;
    int v0 = vblk * 256 + tid * 2;

    {
        const float4* src = (const float4*)g_ctxT;
        float4* dst = (float4*)cst;
#pragma unroll
        for (int it = 0; it < 16; it++) {
            int f = it * 128 + tid;
            int d = f >> 2;
            int j4 = f & 3;
            dst[d * 4 + j4] = src[d * 8 + bh * 4 + j4];
        }
    }
    __syncthreads();

    u64 acc0[8], acc1[8];
#pragma unroll
    for (int j = 0; j < 8; j++) { acc0[j] = 0ull; acc1[j] = 0ull; }

#pragma unroll 16
    for (int dl = 0; dl < 512; dl++) {
        float2 w = *(const float2*)(outw + (size_t)dl * VV + v0);
        u64 w2x = pack_dup(w.x);
        u64 w2y = pack_dup(w.y);
        const u64* cp = (const u64*)(cst + dl * 16);
#pragma unroll
        for (int j = 0; j < 8; j++) {
            u64 c = cp[j];
            acc0[j] = ffma2(w2x, c, acc0[j]);
            acc1[j] = ffma2(w2y, c, acc1[j]);
        }
    }

    float ob0 = outb[v0], ob1 = outb[v0 + 1];
#pragma unroll
    for (int j = 0; j < 8; j++) {
        float a0l, a0h, a1l, a1h;
        unpack2(acc0[j], a0l, a0h);
        unpack2(acc1[j], a1l, a1h);
        int brow = bh * 16 + 2 * j;
        float2 o0; o0.x = a0l + ob0; o0.y = a1l + ob1;
        float2 o1; o1.x = a0h + ob0; o1.y = a1h + ob1;
        *(float2*)(out + (size_t)brow * VV + v0)       = o0;
        *(float2*)(out + (size_t)(brow + 1) * VV + v0) = o1;
    }
}

// ======================= launch =======================
extern "C" void kernel_launch(void* const* d_in, const int* in_sizes, int n_in,
                              void* d_out, int out_size)
{
    const int*   seq   = (const int*)d_in[0];
    const float* embed = (const float*)d_in[1];
    const float* ff1w  = (const float*)d_in[2];
    const float* ff1b  = (const float*)d_in[3];
    const float* ff2w  = (const float*)d_in[4];
    const float* ff2b  = (const float*)d_in[5];
    const float* lng   = (const float*)d_in[6];
    const float* lnb   = (const float*)d_in[7];
    const float* wgw   = (const float*)d_in[8];
    const float* wgb   = (const float*)d_in[9];
    const float* demw  = (const float*)d_in[10];
    const float* demb  = (const float*)d_in[11];
    const float* qw    = (const float*)d_in[12];
    const float* qb    = (const float*)d_in[13];
    const float* outw  = (const float*)d_in[14];
    const float* outb  = (const float*)d_in[15];
    float* out = (float*)d_out;

    float *pAhi, *pAlo, *pYhi, *pYlo, *pW1, *pW2;
    cudaGetSymbolAddress((void**)&pAhi, gAhi);
    cudaGetSymbolAddress((void**)&pAlo, gAlo);
    cudaGetSymbolAddress((void**)&pYhi, gYhi);
    cudaGetSymbolAddress((void**)&pYlo, gYlo);
    cudaGetSymbolAddress((void**)&pW1, gW1);
    cudaGetSymbolAddress((void**)&pW2, gW2);

    static bool attr_done = false;
    if (!attr_done) {
        cudaFuncSetAttribute(mma_gemm<512, true>,   cudaFuncAttributeMaxDynamicSharedMemorySize, SMEM_REQ);
        cudaFuncSetAttribute(mma_gemm<1024, false>, cudaFuncAttributeMaxDynamicSharedMemorySize, SMEM_REQ);
        attr_done = true;
    }

    prep_tok_frag<<<MR / 16, 256>>>(seq, embed);
    prep_w_frag<<<(1024 / 8) * (512 / 8) * 32 / 256, 256>>>(ff1w, 512 / 8, 1024, pW1);
    prep_w_frag<<<(512 / 8) * (1024 / 8) * 32 / 256, 256>>>(ff2w, 1024 / 8, 512, pW2);

    mma_gemm<512, true><<<dim3(1024 / 128, MR / 128), 256, SMEM_REQ>>>(
        pAhi, pAlo, pW1, ff1b, seq, embed);
    mma_gemm<1024, false><<<dim3(512 / 128, MR / 128), 256, SMEM_REQ>>>(
        pYhi, pYlo, pW2, ff2b, seq, embed);

    ln_kernel<<<MR / 8, 256>>>(lng, lnb, wgw, wgb, demw, demb);
    q_kernel<<<dim3(4, BB), 128>>>(qw, qb, lng, lnb);
    readhead_kernel<<<BB, 256>>>(lng, lnb);
    out_kernel<<<250, 128>>>(outw, outb, out);
}